// round 5
// baseline (speedup 1.0000x reference)
#include <cuda_runtime.h>
#include <math.h>

// Problem constants
#define NBATCH 8
#define NPTS   2048
#define NFEAT  32
#define NROWS  (NBATCH * NPTS)                       // 16384
#define NMAT   ((size_t)NBATCH * NPTS * NPTS)        // 33554432
#define MAX_IT 100
#define RB     8                                     // rows per iter block
#define RBLK   (NPTS / RB)                           // 256 row-blocks per batch

// eps = 0.1 ; log2-domain scale: (1/eps) * log2(e)
#define S2   14.4269504088896341f
#define LN2  0.6931471805599453f
#define EPSV 0.1f
#define LOG_MUV (logf(1.0f / 2048.0f + 1e-8f))
#define LOG_NUV LOG_MUV
#define ERR_THRESH_SUM 0.8f

// Scratch (__device__ globals; no allocation allowed)
__device__ __align__(16) float g_u[NROWS];
__device__ __align__(16) float g_v[NROWS];
__device__ float g_err[MAX_IT];
__device__ __align__(16) float g_pl[NBATCH * RBLK * NPTS];   // 16 MB col partial lse (log2)
__device__ __align__(16) float g_pl2[NBATCH * 8 * NPTS];     // stage-2 partials

__device__ __forceinline__ float ex2f(float x) {
    float y;
    asm("ex2.approx.ftz.f32 %0, %1;" : "=f"(y) : "f"(x));
    return y;
}
__device__ __forceinline__ float lg2f(float x) {
    float y;
    asm("lg2.approx.ftz.f32 %0, %1;" : "=f"(y) : "f"(x));
    return y;
}

// ---------------------------------------------------------------------------
// Init
// ---------------------------------------------------------------------------
__global__ void k_init(float* __restrict__ cost) {
    int t = blockIdx.x * blockDim.x + threadIdx.x;
    int n = gridDim.x * blockDim.x;
    for (int i = t; i < NROWS; i += n) {
        g_u[i] = 0.0f;
        g_v[i] = 0.0f;
    }
    if (t < MAX_IT) g_err[t] = 0.0f;
    if (t < NBATCH) cost[t] = 0.0f;
}

// ---------------------------------------------------------------------------
// Cost matrix: C[b,i,j] = sum_d (x[b,i,d] - y[b,j,d])^2
// ---------------------------------------------------------------------------
__global__ void __launch_bounds__(256) k_cost(const float* __restrict__ x,
                                              const float* __restrict__ y,
                                              float* __restrict__ C) {
    __shared__ float xs[NFEAT * 65];
    __shared__ float ys[NFEAT * 65];

    int tile = blockIdx.x;          // 8192 tiles of 64x64
    int b  = tile >> 10;
    int ti = (tile >> 5) & 31;
    int tj = tile & 31;
    int tid = threadIdx.x;

    const float* xb = x + ((size_t)b * NPTS + (size_t)ti * 64) * NFEAT;
    const float* yb = y + ((size_t)b * NPTS + (size_t)tj * 64) * NFEAT;

    for (int e = tid; e < 64 * NFEAT; e += 256) {
        int row = e >> 5;
        int d   = e & 31;
        xs[d * 65 + row] = xb[e];
        ys[d * 65 + row] = yb[e];
    }
    __syncthreads();

    int ri = (tid >> 4) << 2;
    int cj = (tid & 15) << 2;

    float acc[4][4];
#pragma unroll
    for (int a = 0; a < 4; a++)
#pragma unroll
        for (int c = 0; c < 4; c++) acc[a][c] = 0.0f;

#pragma unroll
    for (int d = 0; d < NFEAT; d++) {
        float xa[4], yv[4];
#pragma unroll
        for (int a = 0; a < 4; a++) xa[a] = xs[d * 65 + ri + a];
#pragma unroll
        for (int c = 0; c < 4; c++) yv[c] = ys[d * 65 + cj + c];
#pragma unroll
        for (int a = 0; a < 4; a++)
#pragma unroll
            for (int c = 0; c < 4; c++) {
                float diff = xa[a] - yv[c];
                acc[a][c] = fmaf(diff, diff, acc[a][c]);
            }
    }

    float* Cb = C + (size_t)b * NPTS * NPTS + (size_t)(ti * 64 + ri) * NPTS + (tj * 64 + cj);
#pragma unroll
    for (int a = 0; a < 4; a++) {
        float4 o = make_float4(acc[a][0], acc[a][1], acc[a][2], acc[a][3]);
        *reinterpret_cast<float4*>(Cb + (size_t)a * NPTS) = o;
    }
}

// ---------------------------------------------------------------------------
// Fused iteration: block = 256 threads (8 warps), 8 rows of one batch.
// Phase 1: warp w computes u_new for row w (grouped online LSE, two
//   independent accumulators to break the rescale dependency chain).
// Phase 2: re-read the block's 8 C rows (L2-hot: 64 KB/block working set)
//   and fold into exact per-column online LSE. 4 cols/lane x 2 halves.
// Column partial stored as single log2-domain lse. No t staging in smem.
// Early freeze: g_err[it-1] < thresh (sticky).
// ---------------------------------------------------------------------------
__global__ void __launch_bounds__(256) k_iter(const float* __restrict__ C, int it) {
    if (it > 0 && g_err[it - 1] < ERR_THRESH_SUM) return;

    __shared__ float vS2_s[NPTS];        // 8 KB : v * S2
    __shared__ float uS2_s[RB];
    __shared__ float blkerr;

    int blk = blockIdx.x;                // 8 * 256 = 2048 blocks
    int b   = blk >> 8;
    int rb  = blk & 255;
    int tid = threadIdx.x;
    int w   = tid >> 5;
    int l   = tid & 31;

    const float4* vg  = reinterpret_cast<const float4*>(g_v + (b << 11));
    float4*       vs4 = reinterpret_cast<float4*>(vS2_s);
#pragma unroll
    for (int k = 0; k < 2; k++) {
        float4 t = vg[tid + (k << 8)];
        t.x *= S2; t.y *= S2; t.z *= S2; t.w *= S2;
        vs4[tid + (k << 8)] = t;
    }
    if (tid == 0) blkerr = 0.0f;
    __syncthreads();

    const float* Cb = C + ((size_t)b << 22) + (((size_t)rb * RB) << 11);

    // ---- phase 1: row w ----
    {
        int r = (b << 11) + rb * RB + w;
        const float4* Cr = reinterpret_cast<const float4*>(Cb + ((size_t)w << 11));
        float m0 = -1e30f, s0 = 0.0f, m1 = -1e30f, s1 = 0.0f;
#pragma unroll
        for (int g = 0; g < 8; g += 2) {
#pragma unroll
            for (int h = 0; h < 2; h++) {
                int idx = l + ((g + h) << 6);
                float4 c0 = Cr[idx];
                float4 c1 = Cr[idx + 32];
                float4 v0 = vs4[idx];
                float4 v1 = vs4[idx + 32];
                float t0 = fmaf(-S2, c0.x, v0.x);
                float t1 = fmaf(-S2, c0.y, v0.y);
                float t2 = fmaf(-S2, c0.z, v0.z);
                float t3 = fmaf(-S2, c0.w, v0.w);
                float t4 = fmaf(-S2, c1.x, v1.x);
                float t5 = fmaf(-S2, c1.y, v1.y);
                float t6 = fmaf(-S2, c1.z, v1.z);
                float t7 = fmaf(-S2, c1.w, v1.w);
                float m8 = fmaxf(fmaxf(fmaxf(t0, t1), fmaxf(t2, t3)),
                                 fmaxf(fmaxf(t4, t5), fmaxf(t6, t7)));
                float sum8;
                if (h == 0) {
                    float nm = fmaxf(m0, m8);
                    sum8 = ((ex2f(t0 - nm) + ex2f(t1 - nm)) + (ex2f(t2 - nm) + ex2f(t3 - nm)))
                         + ((ex2f(t4 - nm) + ex2f(t5 - nm)) + (ex2f(t6 - nm) + ex2f(t7 - nm)));
                    s0 = s0 * ex2f(m0 - nm) + sum8;
                    m0 = nm;
                } else {
                    float nm = fmaxf(m1, m8);
                    sum8 = ((ex2f(t0 - nm) + ex2f(t1 - nm)) + (ex2f(t2 - nm) + ex2f(t3 - nm)))
                         + ((ex2f(t4 - nm) + ex2f(t5 - nm)) + (ex2f(t6 - nm) + ex2f(t7 - nm)));
                    s1 = s1 * ex2f(m1 - nm) + sum8;
                    m1 = nm;
                }
            }
        }
        float m = fmaxf(m0, m1);
        float s = s0 * ex2f(m0 - m) + s1 * ex2f(m1 - m);
#pragma unroll
        for (int o = 16; o; o >>= 1) {
            float mo = __shfl_xor_sync(0xffffffffu, m, o);
            float so = __shfl_xor_sync(0xffffffffu, s, o);
            float nm = fmaxf(m, mo);
            s = s * ex2f(m - nm) + so * ex2f(mo - nm);
            m = nm;
        }
        if (l == 0) {
            float lse  = (m + lg2f(s)) * LN2;      // natural-log lse of (v - C)/eps
            float unew = EPSV * (LOG_MUV - lse);
            float du = fabsf(unew - g_u[r]);
            g_u[r]   = unew;
            uS2_s[w] = unew * S2;
            atomicAdd(&blkerr, du);
        }
    }
    __syncthreads();

    // ---- phase 2: per-column exact online LSE over the 8 rows (L2-hot) ----
    float4* po = reinterpret_cast<float4*>(g_pl + ((size_t)blk << 11));

#pragma unroll 1
    for (int half = 0; half < 2; half++) {
        int cq = (half << 8) + (w << 5) + l;       // float4 column index
        float4 vv = vs4[cq];
        float cm[4], cs[4];
#pragma unroll
        for (int q = 0; q < 4; q++) { cm[q] = -1e30f; cs[q] = 0.0f; }

#pragma unroll
        for (int ch = 0; ch < 2; ch++) {
            float4 cc[4];
#pragma unroll
            for (int rr = 0; rr < 4; rr++)
                cc[rr] = reinterpret_cast<const float4*>(Cb + ((size_t)((ch << 2) + rr) << 11))[cq];
            float us0 = uS2_s[(ch << 2) + 0];
            float us1 = uS2_s[(ch << 2) + 1];
            float us2 = uS2_s[(ch << 2) + 2];
            float us3 = uS2_s[(ch << 2) + 3];
#define COLUPD(q, vc, e0, e1, e2, e3)                                          \
            {                                                                  \
                float a0 = fmaf(-S2, (e0), (vc)) + us0;                        \
                float a1 = fmaf(-S2, (e1), (vc)) + us1;                        \
                float a2 = fmaf(-S2, (e2), (vc)) + us2;                        \
                float a3 = fmaf(-S2, (e3), (vc)) + us3;                        \
                float m4 = fmaxf(fmaxf(a0, a1), fmaxf(a2, a3));                \
                float nm = fmaxf(cm[q], m4);                                   \
                cs[q] = cs[q] * ex2f(cm[q] - nm)                               \
                      + ((ex2f(a0 - nm) + ex2f(a1 - nm))                       \
                       + (ex2f(a2 - nm) + ex2f(a3 - nm)));                     \
                cm[q] = nm;                                                    \
            }
            COLUPD(0, vv.x, cc[0].x, cc[1].x, cc[2].x, cc[3].x)
            COLUPD(1, vv.y, cc[0].y, cc[1].y, cc[2].y, cc[3].y)
            COLUPD(2, vv.z, cc[0].z, cc[1].z, cc[2].z, cc[3].z)
            COLUPD(3, vv.w, cc[0].w, cc[1].w, cc[2].w, cc[3].w)
#undef COLUPD
        }
        po[cq] = make_float4(cm[0] + lg2f(cs[0]), cm[1] + lg2f(cs[1]),
                             cm[2] + lg2f(cs[2]), cm[3] + lg2f(cs[3]));
    }
    if (tid == 0) atomicAdd(&g_err[it], blkerr);
}

// ---------------------------------------------------------------------------
// v reduce, stage A: merge 32 log2-domain partials -> 8 per column.
// ---------------------------------------------------------------------------
__global__ void __launch_bounds__(256) k_vredA(int it) {
    if (it > 0 && g_err[it - 1] < ERR_THRESH_SUM) return;
    int t   = blockIdx.x * 256 + threadIdx.x;    // 512 blocks -> 131072 threads
    int col = t & 2047;
    int pg  = (t >> 11) & 7;
    int b   = t >> 14;
    size_t base = (((size_t)(b * RBLK + pg * 32)) << 11) + col;
    float m0 = -1e30f, s0 = 0.0f, m1 = -1e30f, s1 = 0.0f;
#pragma unroll
    for (int k = 0; k < 32; k += 2) {
        float p0 = g_pl[base + ((size_t)k << 11)];
        float p1 = g_pl[base + ((size_t)(k + 1) << 11)];
        float n0 = fmaxf(m0, p0);
        s0 = s0 * ex2f(m0 - n0) + ex2f(p0 - n0);
        m0 = n0;
        float n1 = fmaxf(m1, p1);
        s1 = s1 * ex2f(m1 - n1) + ex2f(p1 - n1);
        m1 = n1;
    }
    float m = fmaxf(m0, m1);
    float s = s0 * ex2f(m0 - m) + s1 * ex2f(m1 - m);
    g_pl2[(((size_t)(b * 8 + pg)) << 11) + col] = m + lg2f(s);
}

// ---------------------------------------------------------------------------
// v reduce, stage B: merge 8 -> v_new = v_old + eps*(log_nu - lse).
// ---------------------------------------------------------------------------
__global__ void __launch_bounds__(256) k_vredB(int it) {
    if (it > 0 && g_err[it - 1] < ERR_THRESH_SUM) return;
    int t   = blockIdx.x * 256 + threadIdx.x;    // 64 blocks -> 16384 threads
    int col = t & 2047;
    int b   = t >> 11;
    size_t base = (((size_t)(b * 8)) << 11) + col;
    float m = -1e30f, s = 0.0f;
#pragma unroll
    for (int k = 0; k < 8; k++) {
        float p = g_pl2[base + ((size_t)k << 11)];
        float nm = fmaxf(m, p);
        s = s * ex2f(m - nm) + ex2f(p - nm);
        m = nm;
    }
    int j = (b << 11) + col;
    // log2-domain lse already includes v (a = (u+v-C)*S2): v_new = v + eps*(log_nu - lse)
    g_v[j] = g_v[j] + EPSV * (LOG_NUV - (m + lg2f(s)) * LN2);
}

// ---------------------------------------------------------------------------
// Epilogue: pi = exp((u_i + v_j - C_ij)/eps), cost[b] = sum pi*C
// ---------------------------------------------------------------------------
__global__ void __launch_bounds__(256) k_pi(const float* __restrict__ C,
                                            float* __restrict__ pi,
                                            float* __restrict__ cost) {
    __shared__ float blkcost;
    if (threadIdx.x == 0) blkcost = 0.0f;
    __syncthreads();

    int warp = (blockIdx.x << 3) + (threadIdx.x >> 5);
    int lane = threadIdx.x & 31;
    int r = warp;
    int b = r >> 11;

    float u = g_u[r];
    const float4* Cr = reinterpret_cast<const float4*>(C + (size_t)r * NPTS);
    const float4* Vr = reinterpret_cast<const float4*>(g_v + (b << 11));
    float4* Pr = reinterpret_cast<float4*>(pi + (size_t)r * NPTS);

    float acc = 0.0f;
#pragma unroll 4
    for (int k = lane; k < NPTS / 4; k += 32) {
        float4 c = Cr[k];
        float4 v = Vr[k];
        float4 p;
        p.x = ex2f((u + v.x - c.x) * S2);
        p.y = ex2f((u + v.y - c.y) * S2);
        p.z = ex2f((u + v.z - c.z) * S2);
        p.w = ex2f((u + v.w - c.w) * S2);
        Pr[k] = p;
        acc += p.x * c.x + p.y * c.y + p.z * c.z + p.w * c.w;
    }
#pragma unroll
    for (int o = 16; o; o >>= 1) acc += __shfl_xor_sync(0xffffffffu, acc, o);
    if (lane == 0) atomicAdd(&blkcost, acc);
    __syncthreads();
    if (threadIdx.x == 0) atomicAdd(&cost[b], blkcost);
}

// ---------------------------------------------------------------------------
// Launch
// ---------------------------------------------------------------------------
extern "C" void kernel_launch(void* const* d_in, const int* in_sizes, int n_in,
                              void* d_out, int out_size) {
    const float* x = (const float*)d_in[0];
    const float* y = (const float*)d_in[1];
    float* out  = (float*)d_out;
    float* cost = out;
    float* pi   = out + NBATCH;
    float* C    = out + NBATCH + NMAT;

    k_init<<<64, 256>>>(cost);
    k_cost<<<NBATCH * 32 * 32, 256>>>(x, y, C);
    for (int it = 0; it < MAX_IT; it++) {
        k_iter<<<NBATCH * RBLK, 256>>>(C, it);
        k_vredA<<<512, 256>>>(it);
        k_vredB<<<64, 256>>>(it);
    }
    k_pi<<<NROWS / 8, 256>>>(C, pi, cost);
}